// round 1
// baseline (speedup 1.0000x reference)
#include <cuda_runtime.h>
#include <math.h>

#define N_NODES 20000
#define N_EDGES 80000
#define DIM 64
#define EDIM 12
#define PCOLS 832   // 12*64 weight blocks + 64 bias block
#define BN_EPS 1e-5f

// ---------------- scratch (device globals; no allocation allowed) ----------------
__device__ float g_P[(size_t)N_NODES * PCOLS];   // 66.56 MB: P = X @ M
__device__ float g_agg[(size_t)N_NODES * DIM];   // scatter-sum of messages
__device__ float g_cnt[N_NODES];                 // edge counts per dst
__device__ float g_sum[EDIM];
__device__ float g_sumsq[EDIM];
__device__ float g_scale[EDIM];                  // rsqrt(var+eps)*gamma
__device__ float g_shift[EDIM];                  // beta - mu*scale

// ---------------- kernel 0: zero scratch ----------------
__global__ void k_zero() {
    int idx = blockIdx.x * blockDim.x + threadIdx.x;
    int stride = gridDim.x * blockDim.x;
    for (int j = idx; j < N_NODES * DIM; j += stride) g_agg[j] = 0.f;
    for (int j = idx; j < N_NODES; j += stride) g_cnt[j] = 0.f;
    if (idx < EDIM) { g_sum[idx] = 0.f; g_sumsq[idx] = 0.f; }
}

// ---------------- kernel 1: BN column sums ----------------
__global__ void k_bn_reduce(const float* __restrict__ ea) {
    float s[EDIM], q[EDIM];
#pragma unroll
    for (int c = 0; c < EDIM; c++) { s[c] = 0.f; q[c] = 0.f; }
    int stride = gridDim.x * blockDim.x;
    for (int e = blockIdx.x * blockDim.x + threadIdx.x; e < N_EDGES; e += stride) {
        const float* row = ea + (size_t)e * EDIM;
#pragma unroll
        for (int c = 0; c < EDIM; c++) { float v = row[c]; s[c] += v; q[c] += v * v; }
    }
#pragma unroll
    for (int off = 16; off > 0; off >>= 1) {
#pragma unroll
        for (int c = 0; c < EDIM; c++) {
            s[c] += __shfl_down_sync(0xffffffffu, s[c], off);
            q[c] += __shfl_down_sync(0xffffffffu, q[c], off);
        }
    }
    __shared__ float bs[2 * EDIM];
    if (threadIdx.x < 2 * EDIM) bs[threadIdx.x] = 0.f;
    __syncthreads();
    if ((threadIdx.x & 31) == 0) {
#pragma unroll
        for (int c = 0; c < EDIM; c++) {
            atomicAdd(&bs[c], s[c]);
            atomicAdd(&bs[EDIM + c], q[c]);
        }
    }
    __syncthreads();
    if (threadIdx.x < EDIM) {
        atomicAdd(&g_sum[threadIdx.x], bs[threadIdx.x]);
        atomicAdd(&g_sumsq[threadIdx.x], bs[EDIM + threadIdx.x]);
    }
}

// ---------------- kernel 2: BN finalize ----------------
__global__ void k_bn_fin(const float* __restrict__ gamma, const float* __restrict__ beta) {
    int c = threadIdx.x;
    if (c < EDIM) {
        float inv_n = 1.0f / (float)N_EDGES;
        float mu = g_sum[c] * inv_n;
        float var = g_sumsq[c] * inv_n - mu * mu;
        float sc = rsqrtf(var + BN_EPS) * gamma[c];
        g_scale[c] = sc;
        g_shift[c] = beta[c] - mu * sc;
    }
}

// ---------------- kernel 3: P = X @ M  (M = rearranged lin_w | lin_b) ----------------
// C[n, k*64+o] = sum_i x[n,i]*lin_w[k, i*64+o];  C[n, 768+o] = sum_i x[n,i]*lin_b[i*64+o]
// Tiles: BM=64, BN=64, K=64 (full). 256 threads, 4x4 microtiles.
__global__ void k_gemm(const float* __restrict__ x, const float* __restrict__ lw,
                       const float* __restrict__ lb) {
    __shared__ float As[64 * 68];  // [m][k], pitch 68 (conflict-free column reads, 16B aligned)
    __shared__ float Bs[64 * 64];  // [k][o]

    int m0 = blockIdx.x * 64;
    int jb = blockIdx.y;  // 0..12  (12 = bias block)
    int tid = threadIdx.x;

#pragma unroll
    for (int r = 0; r < 4; r++) {
        int L = tid + r * 256;         // 0..1023 float4 slots
        int m = L >> 4;                // row in tile
        int kc = (L & 15) << 2;        // col (multiple of 4)
        float4 v = make_float4(0.f, 0.f, 0.f, 0.f);
        int row = m0 + m;
        if (row < N_NODES) v = *(const float4*)&x[(size_t)row * DIM + kc];
        *(float4*)&As[m * 68 + kc] = v;

        // B tile: Bs[i][o] = lin_w[jb*4096 + i*64 + o] (or lin_b for jb==12)
        int i = m;
        int oc = kc;
        float4 b;
        if (jb < 12) b = *(const float4*)&lw[(size_t)jb * 4096 + i * 64 + oc];
        else         b = *(const float4*)&lb[i * 64 + oc];
        *(float4*)&Bs[i * 64 + oc] = b;
    }
    __syncthreads();

    int tn = tid & 15;
    int tm = tid >> 4;
    float acc[4][4];
#pragma unroll
    for (int j = 0; j < 4; j++)
#pragma unroll
        for (int l = 0; l < 4; l++) acc[j][l] = 0.f;

#pragma unroll
    for (int kk = 0; kk < 64; kk++) {
        float4 b4 = *(const float4*)&Bs[kk * 64 + tn * 4];
        float a0 = As[(tm * 4 + 0) * 68 + kk];
        float a1 = As[(tm * 4 + 1) * 68 + kk];
        float a2 = As[(tm * 4 + 2) * 68 + kk];
        float a3 = As[(tm * 4 + 3) * 68 + kk];
        acc[0][0] += a0 * b4.x; acc[0][1] += a0 * b4.y; acc[0][2] += a0 * b4.z; acc[0][3] += a0 * b4.w;
        acc[1][0] += a1 * b4.x; acc[1][1] += a1 * b4.y; acc[1][2] += a1 * b4.z; acc[1][3] += a1 * b4.w;
        acc[2][0] += a2 * b4.x; acc[2][1] += a2 * b4.y; acc[2][2] += a2 * b4.z; acc[2][3] += a2 * b4.w;
        acc[3][0] += a3 * b4.x; acc[3][1] += a3 * b4.y; acc[3][2] += a3 * b4.z; acc[3][3] += a3 * b4.w;
    }

#pragma unroll
    for (int j = 0; j < 4; j++) {
        int row = m0 + tm * 4 + j;
        if (row < N_NODES) {
            *(float4*)&g_P[(size_t)row * PCOLS + jb * 64 + tn * 4] =
                make_float4(acc[j][0], acc[j][1], acc[j][2], acc[j][3]);
        }
    }
}

// ---------------- kernel 4: per-edge message + scatter ----------------
// msg[e,o] = sum_k ebn[k]*P[src, k*64+o] + P[src, 768+o]; atomicAdd into agg[dst]
__global__ void k_edge(const float* __restrict__ ea, const int* __restrict__ ei) {
    int wg = (blockIdx.x * blockDim.x + threadIdx.x) >> 5;
    int lane = threadIdx.x & 31;
    if (wg >= N_EDGES) return;
    int e = wg;
    int src = ei[e];
    int dst = ei[N_EDGES + e];

    float eb = 0.f;
    if (lane < EDIM) eb = ea[(size_t)e * EDIM + lane] * g_scale[lane] + g_shift[lane];

    const float* p = g_P + (size_t)src * PCOLS;
    float acc0 = p[768 + lane];
    float acc1 = p[768 + 32 + lane];
#pragma unroll
    for (int k = 0; k < EDIM; k++) {
        float c = __shfl_sync(0xffffffffu, eb, k);
        acc0 += c * p[k * 64 + lane];
        acc1 += c * p[k * 64 + 32 + lane];
    }
    float* a = g_agg + (size_t)dst * DIM;
    atomicAdd(a + lane, acc0);
    atomicAdd(a + 32 + lane, acc1);
    if (lane == 0) atomicAdd(&g_cnt[dst], 1.0f);
}

// ---------------- kernel 5: mean + relu + GRU ----------------
// warp handles 4 nodes; weights live in smem with pitch 65 (bank-conflict-free)
#define WPITCH 65
#define NB 4
#define NODE_SMEM_FLOATS (2 * 192 * WPITCH + 8 * 2 * NB * 64)

__global__ void k_node(const float* __restrict__ x,
                       const float* __restrict__ wih, const float* __restrict__ whh,
                       const float* __restrict__ bih, const float* __restrict__ bhh,
                       float* __restrict__ out) {
    extern __shared__ float sm[];
    float* ws_ih = sm;                         // 192 x 65
    float* ws_hh = sm + 192 * WPITCH;          // 192 x 65
    float* buf   = sm + 2 * 192 * WPITCH;      // [8 warps][2][NB][64]

    int tid = threadIdx.x;
    // load weights (192*64 elements each)
    for (int idx = tid; idx < 192 * 64; idx += blockDim.x) {
        int g = idx >> 6, i = idx & 63;
        ws_ih[g * WPITCH + i] = wih[idx];
        ws_hh[g * WPITCH + i] = whh[idx];
    }
    __syncthreads();

    int w = tid >> 5;
    int lane = tid & 31;
    float* sm_m = buf + (w * 2 + 0) * NB * 64;
    float* sm_x = buf + (w * 2 + 1) * NB * 64;

    // bias registers: gate g = lane + 32*j
    float bi[6], bh[6];
#pragma unroll
    for (int j = 0; j < 6; j++) {
        bi[j] = bih[lane + 32 * j];
        bh[j] = bhh[lane + 32 * j];
    }

    int warps_total = gridDim.x * (blockDim.x >> 5);
    for (int n0 = (blockIdx.x * (blockDim.x >> 5) + w) * NB; n0 < N_NODES;
         n0 += warps_total * NB) {
#pragma unroll
        for (int b = 0; b < NB; b++) {
            int n = n0 + b;
            float c = fmaxf(g_cnt[n], 1.0f);
            float inv = 1.0f / c;
            float m0v = fmaxf(g_agg[(size_t)n * DIM + lane] * inv, 0.f);
            float m1v = fmaxf(g_agg[(size_t)n * DIM + 32 + lane] * inv, 0.f);
            sm_m[b * 64 + lane] = m0v;
            sm_m[b * 64 + 32 + lane] = m1v;
            sm_x[b * 64 + lane] = x[(size_t)n * DIM + lane];
            sm_x[b * 64 + 32 + lane] = x[(size_t)n * DIM + 32 + lane];
        }
        __syncwarp();

        float gi[6][NB], gh[6][NB];
#pragma unroll
        for (int j = 0; j < 6; j++)
#pragma unroll
            for (int b = 0; b < NB; b++) { gi[j][b] = bi[j]; gh[j][b] = bh[j]; }

#pragma unroll 8
        for (int i = 0; i < 64; i++) {
            float mv[NB], xv[NB];
#pragma unroll
            for (int b = 0; b < NB; b++) { mv[b] = sm_m[b * 64 + i]; xv[b] = sm_x[b * 64 + i]; }
#pragma unroll
            for (int j = 0; j < 6; j++) {
                float wi = ws_ih[(lane + 32 * j) * WPITCH + i];
                float wh = ws_hh[(lane + 32 * j) * WPITCH + i];
#pragma unroll
                for (int b = 0; b < NB; b++) {
                    gi[j][b] += mv[b] * wi;
                    gh[j][b] += xv[b] * wh;
                }
            }
        }

#pragma unroll
        for (int b = 0; b < NB; b++) {
            int n = n0 + b;
            // o = lane : r=j0, z=j2, n=j4
            float r = 1.0f / (1.0f + expf(-(gi[0][b] + gh[0][b])));
            float z = 1.0f / (1.0f + expf(-(gi[2][b] + gh[2][b])));
            float nn = tanhf(gi[4][b] + r * gh[4][b]);
            float xv = sm_x[b * 64 + lane];
            out[(size_t)n * DIM + lane] = (1.0f - z) * nn + z * xv;
            // o = lane+32 : r=j1, z=j3, n=j5
            r = 1.0f / (1.0f + expf(-(gi[1][b] + gh[1][b])));
            z = 1.0f / (1.0f + expf(-(gi[3][b] + gh[3][b])));
            nn = tanhf(gi[5][b] + r * gh[5][b]);
            xv = sm_x[b * 64 + 32 + lane];
            out[(size_t)n * DIM + 32 + lane] = (1.0f - z) * nn + z * xv;
        }
        __syncwarp();
    }
}

// ---------------- host ----------------
extern "C" void kernel_launch(void* const* d_in, const int* in_sizes, int n_in,
                              void* d_out, int out_size) {
    const float* x     = (const float*)d_in[0];
    const int*   ei    = (const int*)d_in[1];
    const float* ea    = (const float*)d_in[2];
    const float* gamma = (const float*)d_in[3];
    const float* beta  = (const float*)d_in[4];
    const float* lw    = (const float*)d_in[5];
    const float* lb    = (const float*)d_in[6];
    const float* wih   = (const float*)d_in[7];
    const float* whh   = (const float*)d_in[8];
    const float* bih   = (const float*)d_in[9];
    const float* bhh   = (const float*)d_in[10];
    float* out = (float*)d_out;

    k_zero<<<1024, 256>>>();
    k_bn_reduce<<<160, 256>>>(ea);
    k_bn_fin<<<1, 32>>>(gamma, beta);

    dim3 g2((N_NODES + 63) / 64, 13);
    k_gemm<<<g2, 256>>>(x, lw, lb);

    k_edge<<<(N_EDGES * 32) / 256, 256>>>(ea, ei);

    size_t node_smem = NODE_SMEM_FLOATS * sizeof(float);
    cudaFuncSetAttribute(k_node, cudaFuncAttributeMaxDynamicSharedMemorySize, (int)node_smem);
    k_node<<<625, 256, node_smem>>>(x, wih, whh, bih, bhh, out);
}

// round 3
// speedup vs baseline: 1.6140x; 1.6140x over previous
#include <cuda_runtime.h>
#include <math.h>

#define N_NODES 20000
#define N_EDGES 80000
#define DIM 64
#define EDIM 12
#define PCOLS 1024   // 12*64 W blocks + 64 bias block + 192 gh (x @ w_hh^T)
#define BCOLS 1216   // PCOLS + 192 (w_ih^T for the gi GEMM)
#define BN_EPS 1e-5f

// ---------------- scratch ----------------
__device__ float g_P[(size_t)N_NODES * PCOLS];   // 81.9 MB
__device__ float g_B[64 * BCOLS];                // packed tf32 weight matrix
__device__ float g_M[(size_t)N_NODES * DIM];     // relu(agg/cnt)
__device__ float g_GI[(size_t)N_NODES * 192];    // m @ w_ih^T
__device__ float g_agg[(size_t)N_NODES * DIM];
__device__ float g_cnt[N_NODES];
__device__ float g_sum[EDIM];
__device__ float g_sumsq[EDIM];
__device__ float g_scale[EDIM];
__device__ float g_shift[EDIM];

__device__ __forceinline__ float f2tf32(float f) {
    unsigned u;
    asm("cvt.rna.tf32.f32 %0, %1;" : "=r"(u) : "f"(f));
    return __uint_as_float(u);
}

// ---------------- kernel 0: zero scratch ----------------
__global__ void k_zero() {
    int idx = blockIdx.x * blockDim.x + threadIdx.x;
    int stride = gridDim.x * blockDim.x;
    for (int j = idx; j < N_NODES * DIM; j += stride) g_agg[j] = 0.f;
    for (int j = idx; j < N_NODES; j += stride) g_cnt[j] = 0.f;
    if (idx < EDIM) { g_sum[idx] = 0.f; g_sumsq[idx] = 0.f; }
}

// ---------------- kernel 1: BN column sums ----------------
__global__ void k_bn_reduce(const float* __restrict__ ea) {
    float s[EDIM], q[EDIM];
#pragma unroll
    for (int c = 0; c < EDIM; c++) { s[c] = 0.f; q[c] = 0.f; }
    int stride = gridDim.x * blockDim.x;
    for (int e = blockIdx.x * blockDim.x + threadIdx.x; e < N_EDGES; e += stride) {
        const float* row = ea + (size_t)e * EDIM;
#pragma unroll
        for (int c = 0; c < EDIM; c++) { float v = row[c]; s[c] += v; q[c] += v * v; }
    }
#pragma unroll
    for (int off = 16; off > 0; off >>= 1) {
#pragma unroll
        for (int c = 0; c < EDIM; c++) {
            s[c] += __shfl_down_sync(0xffffffffu, s[c], off);
            q[c] += __shfl_down_sync(0xffffffffu, q[c], off);
        }
    }
    __shared__ float bs[2 * EDIM];
    if (threadIdx.x < 2 * EDIM) bs[threadIdx.x] = 0.f;
    __syncthreads();
    if ((threadIdx.x & 31) == 0) {
#pragma unroll
        for (int c = 0; c < EDIM; c++) {
            atomicAdd(&bs[c], s[c]);
            atomicAdd(&bs[EDIM + c], q[c]);
        }
    }
    __syncthreads();
    if (threadIdx.x < EDIM) {
        atomicAdd(&g_sum[threadIdx.x], bs[threadIdx.x]);
        atomicAdd(&g_sumsq[threadIdx.x], bs[EDIM + threadIdx.x]);
    }
}

// ---------------- kernel 2: BN finalize ----------------
__global__ void k_bn_fin(const float* __restrict__ gamma, const float* __restrict__ beta) {
    int c = threadIdx.x;
    if (c < EDIM) {
        float inv_n = 1.0f / (float)N_EDGES;
        float mu = g_sum[c] * inv_n;
        float var = g_sumsq[c] * inv_n - mu * mu;
        float sc = rsqrtf(var + BN_EPS) * gamma[c];
        g_scale[c] = sc;
        g_shift[c] = beta[c] - mu * sc;
    }
}

// ---------------- kernel 3: pack B [64 x 1216] (tf32-rounded) ----------------
// cols 0..767   : B[i][k*64+o] = lin_w[k, i*64+o]
// cols 768..831 : B[i][768+o]  = lin_b[i*64+o]
// cols 832..1023: B[i][832+g]  = w_hh[g, i]
// cols 1024..1215: B[i][1024+g] = w_ih[g, i]
__global__ void k_pack_B(const float* __restrict__ lw, const float* __restrict__ lb,
                         const float* __restrict__ whh, const float* __restrict__ wih) {
    int idx = blockIdx.x * blockDim.x + threadIdx.x;
    if (idx >= 64 * BCOLS) return;
    int i = idx / BCOLS;
    int j = idx % BCOLS;
    float v;
    if (j < 768) {
        int k = j >> 6, o = j & 63;
        v = lw[(size_t)k * 4096 + i * 64 + o];
    } else if (j < 832) {
        v = lb[i * 64 + (j - 768)];
    } else if (j < 1024) {
        v = whh[(j - 832) * 64 + i];
    } else {
        v = wih[(j - 1024) * 64 + i];
    }
    g_B[idx] = f2tf32(v);
}

// ---------------- tensor-core GEMM: C[M x Ncols] = A[M x 64] @ B[64 x Ncols] ----------------
// BM=128, BN=128, full K=64 in one tile. 256 threads, 8 warps (4 m x 2 n).
#define GA_PITCH 68
#define GB_PITCH 132
#define GEMM_SMEM_FLOATS (128 * GA_PITCH + 64 * GB_PITCH)

__device__ __forceinline__ void mma_tf32(float* c, const unsigned* a, unsigned b0, unsigned b1) {
    asm volatile(
        "mma.sync.aligned.m16n8k8.row.col.f32.tf32.tf32.f32 "
        "{%0,%1,%2,%3}, {%4,%5,%6,%7}, {%8,%9}, {%0,%1,%2,%3};"
        : "+f"(c[0]), "+f"(c[1]), "+f"(c[2]), "+f"(c[3])
        : "r"(a[0]), "r"(a[1]), "r"(a[2]), "r"(a[3]), "r"(b0), "r"(b1));
}

__device__ __forceinline__ void gemm_tc_body(const float* __restrict__ A,
                                             const float* __restrict__ Bg,
                                             float* __restrict__ C,
                                             int M, int Ncols, int ldc) {
    extern __shared__ float sm[];
    float* As = sm;                      // [128][68] row-major
    float* Bs = sm + 128 * GA_PITCH;     // [64][132] k-major

    int tid = threadIdx.x;
    int m0 = blockIdx.x * 128;
    int n0 = blockIdx.y * 128;

    // load A tile (128 x 64), tf32-round
#pragma unroll
    for (int r = 0; r < 8; r++) {
        int id = r * 256 + tid;          // float4 id, 2048 total
        int m = id >> 4;
        int k4 = (id & 15) << 2;
        float4 v = make_float4(0.f, 0.f, 0.f, 0.f);
        if (m0 + m < M) v = *(const float4*)&A[(size_t)(m0 + m) * 64 + k4];
        v.x = f2tf32(v.x); v.y = f2tf32(v.y); v.z = f2tf32(v.z); v.w = f2tf32(v.w);
        *(float4*)&As[m * GA_PITCH + k4] = v;
    }
    // load B tile (64 x 128), already tf32 (row stride BCOLS)
#pragma unroll
    for (int r = 0; r < 8; r++) {
        int id = r * 256 + tid;
        int k = id >> 5;
        int n4 = (id & 31) << 2;
        float4 v = make_float4(0.f, 0.f, 0.f, 0.f);
        if (n0 + n4 < Ncols) v = *(const float4*)&Bg[(size_t)k * BCOLS + n0 + n4];
        *(float4*)&Bs[k * GB_PITCH + n4] = v;
    }
    __syncthreads();

    int wid = tid >> 5;
    int lane = tid & 31;
    int gid = lane >> 2;
    int tig = lane & 3;
    int warp_m = wid & 3;      // 0..3 -> 32 rows each
    int warp_n = wid >> 2;     // 0..1 -> 64 cols each

    float acc[2][8][4];
#pragma unroll
    for (int mt = 0; mt < 2; mt++)
#pragma unroll
        for (int nt = 0; nt < 8; nt++)
#pragma unroll
            for (int j = 0; j < 4; j++) acc[mt][nt][j] = 0.f;

#pragma unroll
    for (int ks = 0; ks < 8; ks++) {
        int k0 = ks * 8;
        unsigned a[2][4];
#pragma unroll
        for (int mt = 0; mt < 2; mt++) {
            int rowb = warp_m * 32 + mt * 16;
            a[mt][0] = __float_as_uint(As[(rowb + gid) * GA_PITCH + k0 + tig]);
            a[mt][1] = __float_as_uint(As[(rowb + gid + 8) * GA_PITCH + k0 + tig]);
            a[mt][2] = __float_as_uint(As[(rowb + gid) * GA_PITCH + k0 + tig + 4]);
            a[mt][3] = __float_as_uint(As[(rowb + gid + 8) * GA_PITCH + k0 + tig + 4]);
        }
#pragma unroll
        for (int nt = 0; nt < 8; nt++) {
            int nb = warp_n * 64 + nt * 8 + gid;
            unsigned b0 = __float_as_uint(Bs[(k0 + tig) * GB_PITCH + nb]);
            unsigned b1 = __float_as_uint(Bs[(k0 + tig + 4) * GB_PITCH + nb]);
            mma_tf32(acc[0][nt], a[0], b0, b1);
            mma_tf32(acc[1][nt], a[1], b0, b1);
        }
    }

    // epilogue
#pragma unroll
    for (int mt = 0; mt < 2; mt++) {
#pragma unroll
        for (int nt = 0; nt < 8; nt++) {
            int col = n0 + warp_n * 64 + nt * 8 + tig * 2;
            if (col >= Ncols) continue;
            int r0 = m0 + warp_m * 32 + mt * 16 + gid;
            if (r0 < M)
                *(float2*)&C[(size_t)r0 * ldc + col] = make_float2(acc[mt][nt][0], acc[mt][nt][1]);
            int r1 = r0 + 8;
            if (r1 < M)
                *(float2*)&C[(size_t)r1 * ldc + col] = make_float2(acc[mt][nt][2], acc[mt][nt][3]);
        }
    }
}

// GEMM1: P = X @ B[:, 0:1024]
__global__ void k_gemm1(const float* __restrict__ x) {
    gemm_tc_body(x, g_B, g_P, N_NODES, PCOLS, PCOLS);
}
// GEMM2: GI = M @ B[:, 1024:1216]
__global__ void k_gemm2() {
    gemm_tc_body(g_M, g_B + 1024, g_GI, N_NODES, 192, 192);
}

// ---------------- kernel: per-edge message + scatter ----------------
__global__ void k_edge(const float* __restrict__ ea, const int* __restrict__ ei) {
    int wg = (blockIdx.x * blockDim.x + threadIdx.x) >> 5;
    int lane = threadIdx.x & 31;
    if (wg >= N_EDGES) return;
    int e = wg;
    int src = ei[e];
    int dst = ei[N_EDGES + e];

    float eb = 0.f;
    if (lane < EDIM) eb = ea[(size_t)e * EDIM + lane] * g_scale[lane] + g_shift[lane];

    const float* p = g_P + (size_t)src * PCOLS;
    float acc0 = p[768 + lane];
    float acc1 = p[768 + 32 + lane];
#pragma unroll
    for (int k = 0; k < EDIM; k++) {
        float c = __shfl_sync(0xffffffffu, eb, k);
        acc0 += c * p[k * 64 + lane];
        acc1 += c * p[k * 64 + 32 + lane];
    }
    float* a = g_agg + (size_t)dst * DIM;
    atomicAdd(a + lane, acc0);
    atomicAdd(a + 32 + lane, acc1);
    if (lane == 0) atomicAdd(&g_cnt[dst], 1.0f);
}

// ---------------- kernel: m = relu(agg) / max(cnt,1) ----------------
__global__ void k_mrelu() {
    int idx = blockIdx.x * blockDim.x + threadIdx.x;
    if (idx >= N_NODES * DIM) return;
    int n = idx >> 6;
    float c = fmaxf(g_cnt[n], 1.0f);
    g_M[idx] = fmaxf(g_agg[idx] / c, 0.f);
}

// ---------------- kernel: elementwise GRU ----------------
__global__ void k_out(const float* __restrict__ x,
                      const float* __restrict__ bih, const float* __restrict__ bhh,
                      float* __restrict__ out) {
    int idx = blockIdx.x * blockDim.x + threadIdx.x;
    if (idx >= N_NODES * DIM) return;
    int n = idx >> 6;
    int o = idx & 63;

    const float* gi = g_GI + (size_t)n * 192;
    const float* gh = g_P + (size_t)n * PCOLS + 832;

    float ir = gi[o] + bih[o];
    float iz = gi[64 + o] + bih[64 + o];
    float in_ = gi[128 + o] + bih[128 + o];
    float hr = gh[o] + bhh[o];
    float hz = gh[64 + o] + bhh[64 + o];
    float hn = gh[128 + o] + bhh[128 + o];

    float r = 1.0f / (1.0f + __expf(-(ir + hr)));
    float z = 1.0f / (1.0f + __expf(-(iz + hz)));
    float nn = tanhf(in_ + r * hn);
    float xv = x[idx];
    out[idx] = (1.0f - z) * nn + z * xv;
}

// ---------------- host ----------------
extern "C" void kernel_launch(void* const* d_in, const int* in_sizes, int n_in,
                              void* d_out, int out_size) {
    const float* x     = (const float*)d_in[0];
    const int*   ei    = (const int*)d_in[1];
    const float* ea    = (const float*)d_in[2];
    const float* gamma = (const float*)d_in[3];
    const float* beta  = (const float*)d_in[4];
    const float* lw    = (const float*)d_in[5];
    const float* lb    = (const float*)d_in[6];
    const float* wih   = (const float*)d_in[7];
    const float* whh   = (const float*)d_in[8];
    const float* bih   = (const float*)d_in[9];
    const float* bhh   = (const float*)d_in[10];
    float* out = (float*)d_out;

    size_t gsmem = GEMM_SMEM_FLOATS * sizeof(float);
    cudaFuncSetAttribute(k_gemm1, cudaFuncAttributeMaxDynamicSharedMemorySize, (int)gsmem);
    cudaFuncSetAttribute(k_gemm2, cudaFuncAttributeMaxDynamicSharedMemorySize, (int)gsmem);

    k_zero<<<512, 256>>>();
    k_bn_reduce<<<160, 256>>>(ea);
    k_bn_fin<<<1, 32>>>(gamma, beta);
    k_pack_B<<<(64 * BCOLS + 255) / 256, 256>>>(lw, lb, whh, wih);

    {
        dim3 g((N_NODES + 127) / 128, PCOLS / 128);
        k_gemm1<<<g, 256, gsmem>>>(x);
    }

    k_edge<<<(N_EDGES * 32) / 256, 256>>>(ea, ei);
    k_mrelu<<<(N_NODES * DIM + 255) / 256, 256>>>();

    {
        dim3 g((N_NODES + 127) / 128, 2);
        k_gemm2<<<g, 256, gsmem>>>();
    }

    k_out<<<(N_NODES * DIM + 255) / 256, 256>>>(x, bih, bhh, out);
}